// round 14
// baseline (speedup 1.0000x reference)
#include <cuda_runtime.h>
#include <cuda_bf16.h>
#include <math.h>
#include <stdint.h>

#define BB 64
#define SS 2048
#define HH 128
#define MM (BB*SS)   // 131072

// Scratch (no cudaMalloc allowed).
__device__ float g_xi[BB * SS * HH];
__device__ float g_h [BB * SS * HH];
// Weight tiles transposed to [n][k] row-major, split bf16 hi/lo.
__device__ __nv_bfloat16 g_wi_hi[HH * HH];
__device__ __nv_bfloat16 g_wi_lo[HH * HH];
__device__ __nv_bfloat16 g_wo_hi[HH * HH];
__device__ __nv_bfloat16 g_wo_lo[HH * HH];

__device__ __forceinline__ uint32_t smem_u32(const void* p) {
    uint32_t a;
    asm("{ .reg .u64 t; cvta.to.shared.u64 t, %1; cvt.u32.u64 %0, t; }"
        : "=r"(a) : "l"(p));
    return a;
}

__device__ __forceinline__ void mma_bf16(float* c, uint32_t a0, uint32_t a1,
                                         uint32_t a2, uint32_t a3,
                                         uint32_t b0, uint32_t b1) {
    asm volatile(
        "mma.sync.aligned.m16n8k16.row.col.f32.bf16.bf16.f32 "
        "{%0,%1,%2,%3}, {%4,%5,%6,%7}, {%8,%9}, {%0,%1,%2,%3};"
        : "+f"(c[0]), "+f"(c[1]), "+f"(c[2]), "+f"(c[3])
        : "r"(a0), "r"(a1), "r"(a2), "r"(a3), "r"(b0), "r"(b1));
}

// ldmatrix x4: lane i supplies the address of row (i&7) of block (i>>3).
__device__ __forceinline__ void ldsm4(uint32_t& r0, uint32_t& r1,
                                      uint32_t& r2, uint32_t& r3, uint32_t addr) {
    asm volatile("ldmatrix.sync.aligned.m8n8.x4.shared.b16 {%0,%1,%2,%3}, [%4];"
                 : "=r"(r0), "=r"(r1), "=r"(r2), "=r"(r3) : "r"(addr));
}

// cvt.rn.bf16x2.f32: result = {hi16 = bf16(yh), lo16 = bf16(xl)}.
__device__ __forceinline__ uint32_t cvt_bf16x2(float xl, float yh) {
    uint32_t d;
    asm("cvt.rn.bf16x2.f32 %0, %1, %2;" : "=r"(d) : "f"(yh), "f"(xl));
    return d;
}

// ---------------------------------------------------------------------------
// Prep: W[k][n] (row-major KxN) -> Wt[n][k] row-major, split bf16 hi/lo.
// Grid-parallel: one-time cost is noise.
// ---------------------------------------------------------------------------
__global__ void prep_weights(const float* __restrict__ Wi,
                             const float* __restrict__ Wo) {
    int idx = blockIdx.x * blockDim.x + threadIdx.x;
    if (idx >= HH * HH) return;
    int n = idx >> 7, k = idx & 127;
    {
        float v = Wi[k * HH + n];
        __nv_bfloat16 hi = __float2bfloat16(v);
        g_wi_hi[idx] = hi;
        g_wi_lo[idx] = __float2bfloat16(v - __bfloat162float(hi));
    }
    {
        float v = Wo[k * HH + n];
        __nv_bfloat16 hi = __float2bfloat16(v);
        g_wo_hi[idx] = hi;
        g_wo_lo[idx] = __float2bfloat16(v - __bfloat162float(hi));
    }
}

// ---------------------------------------------------------------------------
// Tensor-core split-bf16 GEMM (mma.sync + ldmatrix, base-target PTX):
//   C[M,128] = A[M,128] @ W + bias; 3 terms Ah*Wh + Ah*Wl + Al*Wh, fp32 acc.
// A hi/lo split by truncation bit-tricks (byte_perm + exact residual).
// CTA: 128 rows x 128 cols, 256 threads; warp w -> m16 strip.
// Pitch PW=68 u32 words/row: 16B-aligned ldmatrix rows, conflict-free LDS.
// (Unchanged from R12: measured 53.3us.)
// ---------------------------------------------------------------------------
#define PW 68
#define TILE_W (HH * PW * 4)       // 34816 B per bf16x2 tile
#define SM_BIAS 0
#define SM_AHI  512
#define SM_ALO  (SM_AHI + TILE_W)
#define SM_WHI  (SM_ALO + TILE_W)
#define SM_WLO  (SM_WHI + TILE_W)
#define SM_TOT  (SM_WLO + TILE_W)  // ~137 KB

__global__ __launch_bounds__(256) void gemm_wt(const float* __restrict__ A,
                                               const __nv_bfloat16* __restrict__ Whi,
                                               const __nv_bfloat16* __restrict__ Wlo,
                                               const float* __restrict__ bias,
                                               float* __restrict__ C) {
    extern __shared__ char smem[];
    uint32_t* sAhi  = (uint32_t*)(smem + SM_AHI);
    uint32_t* sAlo  = (uint32_t*)(smem + SM_ALO);
    uint32_t* sWhi  = (uint32_t*)(smem + SM_WHI);
    uint32_t* sWlo  = (uint32_t*)(smem + SM_WLO);
    float*    sbias = (float*)(smem + SM_BIAS);

    const int tid = threadIdx.x;
    const int wid = tid >> 5;
    const int l   = tid & 31;
    const int row0 = blockIdx.x * 128;

    // Weights: linear copy from pre-transposed global, re-pitch to PW.
    {
        const uint32_t* wh = (const uint32_t*)Whi;
        const uint32_t* wl = (const uint32_t*)Wlo;
#pragma unroll
        for (int i = 0; i < 32; i++) {
            int w   = tid + i * 256;            // 0..8191 u32 words
            int row = w >> 6, col = w & 63;
            sWhi[row * PW + col] = wh[w];
            sWlo[row * PW + col] = wl[w];
        }
    }
    if (tid < 32) ((float4*)sbias)[tid] = ((const float4*)bias)[tid];

    // A tile: coalesced float4 loads -> truncation hi/lo split -> pitched stores.
    {
        const float4* Ag = (const float4*)(A + (size_t)row0 * HH);
#pragma unroll
        for (int i = 0; i < 16; i++) {
            int f4  = tid + i * 256;            // 0..4095
            int row = f4 >> 5;
            int c4  = f4 & 31;
            float4 v = Ag[f4];
            uint32_t bx = __float_as_uint(v.x), by = __float_as_uint(v.y);
            uint32_t bz = __float_as_uint(v.z), bw = __float_as_uint(v.w);
            uint32_t hi01 = __byte_perm(bx, by, 0x7632);
            uint32_t hi23 = __byte_perm(bz, bw, 0x7632);
            float lx = v.x - __uint_as_float(bx & 0xFFFF0000u);
            float ly = v.y - __uint_as_float(by & 0xFFFF0000u);
            float lz = v.z - __uint_as_float(bz & 0xFFFF0000u);
            float lw = v.w - __uint_as_float(bw & 0xFFFF0000u);
            uint32_t lo01 = cvt_bf16x2(lx, ly);
            uint32_t lo23 = cvt_bf16x2(lz, lw);
            int wo = row * PW + c4 * 2;
            *(uint2*)(sAhi + wo) = make_uint2(hi01, hi23);
            *(uint2*)(sAlo + wo) = make_uint2(lo01, lo23);
        }
    }
    __syncthreads();

    // Warp tile: m16 strip, 16 n8 tiles (8 ldmatrix pairs), 8 k16 steps, 3 terms.
    const int m0 = wid * 16;
    const int ra = (m0 + (l >> 2)) * PW + (l & 3);      // A frag base (word)

    const int l8 = l & 7, lb = l >> 3;
    const int bword = ((lb >> 1) * 8 + l8) * PW + (lb & 1) * 4;
    const uint32_t sb = smem_u32(smem);
    const uint32_t addrBhi = sb + SM_WHI + bword * 4;
    const uint32_t addrBlo = sb + SM_WLO + bword * 4;

    float acc[16][4];
#pragma unroll
    for (int nt = 0; nt < 16; nt++)
#pragma unroll
        for (int q = 0; q < 4; q++) acc[nt][q] = 0.f;

#pragma unroll
    for (int ks = 0; ks < 8; ks++) {
        const int kw = ks * 8;                          // k16 = 8 u32 words
        uint32_t ah0 = sAhi[ra + kw];
        uint32_t ah1 = sAhi[ra + 8 * PW + kw];
        uint32_t ah2 = sAhi[ra + kw + 4];
        uint32_t ah3 = sAhi[ra + 8 * PW + kw + 4];
        uint32_t al0 = sAlo[ra + kw];
        uint32_t al1 = sAlo[ra + 8 * PW + kw];
        uint32_t al2 = sAlo[ra + kw + 4];
        uint32_t al3 = sAlo[ra + 8 * PW + kw + 4];
#pragma unroll
        for (int p = 0; p < 8; p++) {
            const uint32_t ofs = (uint32_t)(p * 16 * PW + kw) * 4;
            uint32_t bh0, bh1, bh2, bh3, bl0, bl1, bl2, bl3;
            ldsm4(bh0, bh1, bh2, bh3, addrBhi + ofs);
            ldsm4(bl0, bl1, bl2, bl3, addrBlo + ofs);
            mma_bf16(acc[2 * p],     ah0, ah1, ah2, ah3, bh0, bh1);
            mma_bf16(acc[2 * p],     ah0, ah1, ah2, ah3, bl0, bl1);
            mma_bf16(acc[2 * p],     al0, al1, al2, al3, bh0, bh1);
            mma_bf16(acc[2 * p + 1], ah0, ah1, ah2, ah3, bh2, bh3);
            mma_bf16(acc[2 * p + 1], ah0, ah1, ah2, ah3, bl2, bl3);
            mma_bf16(acc[2 * p + 1], al0, al1, al2, al3, bh2, bh3);
        }
    }

    // Epilogue: c0,c1 -> (row, col..col+1); c2,c3 -> (row+8, ...).
    {
        const int rlo = row0 + m0 + (l >> 2);
        const int col0 = (l & 3) * 2;
#pragma unroll
        for (int nt = 0; nt < 16; nt++) {
            int col = nt * 8 + col0;
            float2 b01 = {sbias[col], sbias[col + 1]};
            float2 o0 = {acc[nt][0] + b01.x, acc[nt][1] + b01.y};
            float2 o1 = {acc[nt][2] + b01.x, acc[nt][3] + b01.y};
            *(float2*)(C + (size_t)rlo * HH + col)       = o0;
            *(float2*)(C + (size_t)(rlo + 8) * HH + col) = o1;
        }
    }
}

// ---------------------------------------------------------------------------
// Recurrence: R3 skeleton, byte-identical structure (one CTA/sequence,
// thread j owns column j with Wh[:,j] in registers, h broadcast via shared,
// TWO barriers per step, 1-deep xi prefetch, no prescaling).
// ONE variable changed vs the measured-926us kernel: tanhf -> MUFU
// ex2+rcp (tanh(x) = 1 - 2/(2^(x*2log2e)+1); ex2 saturates, rcp(inf)=0,
// so the limits are exact and no clamp is needed).
// ---------------------------------------------------------------------------
__global__ __launch_bounds__(128) void rnn_kernel(const float* __restrict__ Wh) {
    __shared__ __align__(16) float sh[HH];
    const int b = blockIdx.x;
    const int j = threadIdx.x;

    float w[HH];
#pragma unroll
    for (int k = 0; k < HH; k++) w[k] = Wh[k * HH + j];

    sh[j] = 0.f;
    const float* xip = g_xi + (size_t)b * SS * HH + j;
    float*       hp  = g_h  + (size_t)b * SS * HH + j;
    __syncthreads();

    float xi_cur = xip[0];
    for (int s = 0; s < SS; s++) {
        float xi_next = (s + 1 < SS) ? xip[(size_t)(s + 1) * HH] : 0.f;

        float a0 = xi_cur, a1 = 0.f, a2 = 0.f, a3 = 0.f;
        const float4* sh4 = (const float4*)sh;
#pragma unroll
        for (int k4 = 0; k4 < HH / 4; k4++) {
            float4 hv = sh4[k4];
            a0 = fmaf(hv.x, w[4 * k4 + 0], a0);
            a1 = fmaf(hv.y, w[4 * k4 + 1], a1);
            a2 = fmaf(hv.z, w[4 * k4 + 2], a2);
            a3 = fmaf(hv.w, w[4 * k4 + 3], a3);
        }
        float v  = (a0 + a1) + (a2 + a3);

        // --- the ONLY change vs R3: MUFU tanh ---
        float e;
        asm("ex2.approx.f32 %0, %1;" : "=f"(e) : "f"(v * 2.885390082f));
        float r;
        asm("rcp.approx.f32 %0, %1;" : "=f"(r) : "f"(e + 1.f));
        float hn = fmaxf(fmaf(-2.f, r, 1.f), 0.f);
        // ----------------------------------------

        __syncthreads();
        sh[j] = hn;
        hp[(size_t)s * HH] = hn;
        xi_cur = xi_next;
        __syncthreads();
    }
}

extern "C" void kernel_launch(void* const* d_in, const int* in_sizes, int n_in,
                              void* d_out, int out_size) {
    const float* x  = (const float*)d_in[0];
    const float* Wi = (const float*)d_in[1];
    const float* Wh = (const float*)d_in[2];
    const float* b  = (const float*)d_in[3];
    const float* Wo = (const float*)d_in[4];
    const float* bo = (const float*)d_in[5];
    float* y = (float*)d_out;

    float *xi_ptr, *h_ptr;
    __nv_bfloat16 *wih, *wil, *woh, *wol;
    cudaGetSymbolAddress((void**)&xi_ptr, g_xi);
    cudaGetSymbolAddress((void**)&h_ptr,  g_h);
    cudaGetSymbolAddress((void**)&wih, g_wi_hi);
    cudaGetSymbolAddress((void**)&wil, g_wi_lo);
    cudaGetSymbolAddress((void**)&woh, g_wo_hi);
    cudaGetSymbolAddress((void**)&wol, g_wo_lo);

    cudaFuncSetAttribute(gemm_wt, cudaFuncAttributeMaxDynamicSharedMemorySize,
                         SM_TOT);

    prep_weights<<<(HH * HH + 255) / 256, 256>>>(Wi, Wo);
    gemm_wt<<<MM / 128, 256, SM_TOT>>>(x, wih, wil, b, xi_ptr);
    rnn_kernel<<<BB, 128>>>(Wh);
    gemm_wt<<<MM / 128, 256, SM_TOT>>>(h_ptr, woh, wol, bo, y);
}

// round 15
// speedup vs baseline: 1.0508x; 1.0508x over previous
#include <cuda_runtime.h>
#include <cuda_bf16.h>
#include <math.h>
#include <stdint.h>

#define BB 64
#define SS 2048
#define HH 128
#define MM (BB*SS)   // 131072
#define MT 64        // GEMM M-tile rows per CTA (2 CTAs/SM)

// Scratch (no cudaMalloc allowed).
__device__ float g_xi[BB * SS * HH];
__device__ float g_h [BB * SS * HH];
// Weight tiles transposed to [n][k] row-major, split bf16 hi/lo.
__device__ __nv_bfloat16 g_wi_hi[HH * HH];
__device__ __nv_bfloat16 g_wi_lo[HH * HH];
__device__ __nv_bfloat16 g_wo_hi[HH * HH];
__device__ __nv_bfloat16 g_wo_lo[HH * HH];

__device__ __forceinline__ uint32_t smem_u32(const void* p) {
    uint32_t a;
    asm("{ .reg .u64 t; cvta.to.shared.u64 t, %1; cvt.u32.u64 %0, t; }"
        : "=r"(a) : "l"(p));
    return a;
}

__device__ __forceinline__ void mma_bf16(float* c, uint32_t a0, uint32_t a1,
                                         uint32_t a2, uint32_t a3,
                                         uint32_t b0, uint32_t b1) {
    asm volatile(
        "mma.sync.aligned.m16n8k16.row.col.f32.bf16.bf16.f32 "
        "{%0,%1,%2,%3}, {%4,%5,%6,%7}, {%8,%9}, {%0,%1,%2,%3};"
        : "+f"(c[0]), "+f"(c[1]), "+f"(c[2]), "+f"(c[3])
        : "r"(a0), "r"(a1), "r"(a2), "r"(a3), "r"(b0), "r"(b1));
}

__device__ __forceinline__ void ldsm4(uint32_t& r0, uint32_t& r1,
                                      uint32_t& r2, uint32_t& r3, uint32_t addr) {
    asm volatile("ldmatrix.sync.aligned.m8n8.x4.shared.b16 {%0,%1,%2,%3}, [%4];"
                 : "=r"(r0), "=r"(r1), "=r"(r2), "=r"(r3) : "r"(addr));
}

__device__ __forceinline__ uint32_t cvt_bf16x2(float xl, float yh) {
    uint32_t d;
    asm("cvt.rn.bf16x2.f32 %0, %1, %2;" : "=r"(d) : "f"(yh), "f"(xl));
    return d;
}

__device__ __forceinline__ void cp_async16(uint32_t smem_addr, const void* gptr) {
    asm volatile("cp.async.cg.shared.global [%0], [%1], 16;"
                 :: "r"(smem_addr), "l"(gptr) : "memory");
}
__device__ __forceinline__ void cp_async_wait_all() {
    asm volatile("cp.async.commit_group;\n\tcp.async.wait_group 0;" ::: "memory");
}

// ---------------------------------------------------------------------------
// Prep: W[k][n] (row-major KxN) -> Wt[n][k] row-major, split bf16 hi/lo.
// ---------------------------------------------------------------------------
__global__ void prep_weights(const float* __restrict__ Wi,
                             const float* __restrict__ Wo) {
    int idx = blockIdx.x * blockDim.x + threadIdx.x;
    if (idx >= HH * HH) return;
    int n = idx >> 7, k = idx & 127;
    {
        float v = Wi[k * HH + n];
        __nv_bfloat16 hi = __float2bfloat16(v);
        g_wi_hi[idx] = hi;
        g_wi_lo[idx] = __float2bfloat16(v - __bfloat162float(hi));
    }
    {
        float v = Wo[k * HH + n];
        __nv_bfloat16 hi = __float2bfloat16(v);
        g_wo_hi[idx] = hi;
        g_wo_lo[idx] = __float2bfloat16(v - __bfloat162float(hi));
    }
}

// ---------------------------------------------------------------------------
// Tensor-core split-bf16 GEMM (mma.sync + ldmatrix):
//   C[M,128] = A[M,128] @ W + bias; 3 terms Ah*Wh + Ah*Wl + Al*Wh, fp32 acc.
// R15: M-tile = 64 rows, 128 threads, ~105 KB smem -> 2 CTAs/SM so two CTAs'
// load/compute phases interleave. Weights fetched with cp.async (overlaps the
// A-tile fp32->hi/lo conversion). Warp-tile math identical to the 53us kernel.
// ---------------------------------------------------------------------------
#define PW 68
#define A_TILE_W (MT * PW * 4)     // 17408 B per A bf16x2 tile
#define W_TILE_W (HH * PW * 4)     // 34816 B per W bf16x2 tile
#define SM_BIAS 0
#define SM_AHI  512
#define SM_ALO  (SM_AHI + A_TILE_W)
#define SM_WHI  (SM_ALO + A_TILE_W)
#define SM_WLO  (SM_WHI + W_TILE_W)
#define SM_TOT  (SM_WLO + W_TILE_W)  // ~105 KB

__global__ __launch_bounds__(128, 2) void gemm_wt(const float* __restrict__ A,
                                                  const __nv_bfloat16* __restrict__ Whi,
                                                  const __nv_bfloat16* __restrict__ Wlo,
                                                  const float* __restrict__ bias,
                                                  float* __restrict__ C) {
    extern __shared__ char smem[];
    uint32_t* sAhi  = (uint32_t*)(smem + SM_AHI);
    uint32_t* sAlo  = (uint32_t*)(smem + SM_ALO);
    float*    sbias = (float*)(smem + SM_BIAS);

    const int tid = threadIdx.x;          // 0..127
    const int wid = tid >> 5;             // 0..3
    const int l   = tid & 31;
    const int row0 = blockIdx.x * MT;
    const uint32_t sb = smem_u32(smem);

    // Weights via cp.async: 2 tiles x 2048 16B-chunks, re-pitched 64 -> 68.
    // chunk ch (0..2047): row = ch>>4, c4 = ch&15 (16B = 4 words).
    {
        const char* wh = (const char*)Whi;
        const char* wl = (const char*)Wlo;
#pragma unroll
        for (int i = 0; i < 16; i++) {
            int ch  = tid + i * 128;               // 0..2047
            int row = ch >> 4, c4 = ch & 15;
            uint32_t dofs = (uint32_t)(row * PW + c4 * 4) * 4;
            uint32_t gofs = (uint32_t)ch * 16;
            cp_async16(sb + SM_WHI + dofs, wh + gofs);
            cp_async16(sb + SM_WLO + dofs, wl + gofs);
        }
    }
    if (tid < 32) ((float4*)sbias)[tid] = ((const float4*)bias)[tid];

    // A tile (64x128 fp32): coalesced float4 loads -> truncation hi/lo split
    // -> pitched stores. Overlaps the in-flight weight cp.asyncs.
    {
        const float4* Ag = (const float4*)(A + (size_t)row0 * HH);
#pragma unroll
        for (int i = 0; i < 16; i++) {
            int f4  = tid + i * 128;               // 0..2047
            int row = f4 >> 5;
            int c4  = f4 & 31;
            float4 v = Ag[f4];
            uint32_t bx = __float_as_uint(v.x), by = __float_as_uint(v.y);
            uint32_t bz = __float_as_uint(v.z), bw = __float_as_uint(v.w);
            uint32_t hi01 = __byte_perm(bx, by, 0x7632);
            uint32_t hi23 = __byte_perm(bz, bw, 0x7632);
            float lx = v.x - __uint_as_float(bx & 0xFFFF0000u);
            float ly = v.y - __uint_as_float(by & 0xFFFF0000u);
            float lz = v.z - __uint_as_float(bz & 0xFFFF0000u);
            float lw = v.w - __uint_as_float(bw & 0xFFFF0000u);
            uint32_t lo01 = cvt_bf16x2(lx, ly);
            uint32_t lo23 = cvt_bf16x2(lz, lw);
            int wo = row * PW + c4 * 2;
            *(uint2*)(sAhi + wo) = make_uint2(hi01, hi23);
            *(uint2*)(sAlo + wo) = make_uint2(lo01, lo23);
        }
    }
    cp_async_wait_all();
    __syncthreads();

    // Warp tile: m16 strip (wid*16), 16 n8 tiles (8 ldmatrix pairs), 8 k16
    // steps, 3 terms. Identical math to the measured-53us kernel.
    const int m0 = wid * 16;
    const int ra = (m0 + (l >> 2)) * PW + (l & 3);

    const int l8 = l & 7, lb = l >> 3;
    const int bword = ((lb >> 1) * 8 + l8) * PW + (lb & 1) * 4;
    const uint32_t addrBhi = sb + SM_WHI + bword * 4;
    const uint32_t addrBlo = sb + SM_WLO + bword * 4;

    float acc[16][4];
#pragma unroll
    for (int nt = 0; nt < 16; nt++)
#pragma unroll
        for (int q = 0; q < 4; q++) acc[nt][q] = 0.f;

#pragma unroll
    for (int ks = 0; ks < 8; ks++) {
        const int kw = ks * 8;
        uint32_t ah0 = sAhi[ra + kw];
        uint32_t ah1 = sAhi[ra + 8 * PW + kw];
        uint32_t ah2 = sAhi[ra + kw + 4];
        uint32_t ah3 = sAhi[ra + 8 * PW + kw + 4];
        uint32_t al0 = sAlo[ra + kw];
        uint32_t al1 = sAlo[ra + 8 * PW + kw];
        uint32_t al2 = sAlo[ra + kw + 4];
        uint32_t al3 = sAlo[ra + 8 * PW + kw + 4];
#pragma unroll
        for (int p = 0; p < 8; p++) {
            const uint32_t ofs = (uint32_t)(p * 16 * PW + kw) * 4;
            uint32_t bh0, bh1, bh2, bh3, bl0, bl1, bl2, bl3;
            ldsm4(bh0, bh1, bh2, bh3, addrBhi + ofs);
            ldsm4(bl0, bl1, bl2, bl3, addrBlo + ofs);
            mma_bf16(acc[2 * p],     ah0, ah1, ah2, ah3, bh0, bh1);
            mma_bf16(acc[2 * p],     ah0, ah1, ah2, ah3, bl0, bl1);
            mma_bf16(acc[2 * p],     al0, al1, al2, al3, bh0, bh1);
            mma_bf16(acc[2 * p + 1], ah0, ah1, ah2, ah3, bh2, bh3);
            mma_bf16(acc[2 * p + 1], ah0, ah1, ah2, ah3, bl2, bl3);
            mma_bf16(acc[2 * p + 1], al0, al1, al2, al3, bh2, bh3);
        }
    }

    // Epilogue: c0,c1 -> (row, col..col+1); c2,c3 -> (row+8, ...).
    {
        const int rlo = row0 + m0 + (l >> 2);
        const int col0 = (l & 3) * 2;
#pragma unroll
        for (int nt = 0; nt < 16; nt++) {
            int col = nt * 8 + col0;
            float2 b01 = {sbias[col], sbias[col + 1]};
            float2 o0 = {acc[nt][0] + b01.x, acc[nt][1] + b01.y};
            float2 o1 = {acc[nt][2] + b01.x, acc[nt][3] + b01.y};
            *(float2*)(C + (size_t)rlo * HH + col)       = o0;
            *(float2*)(C + (size_t)(rlo + 8) * HH + col) = o1;
        }
    }
}

// ---------------------------------------------------------------------------
// Recurrence: EXACT R3 kernel — FROZEN. (Measured 926us; all six attempted
// variations, including MUFU tanh alone, regressed.) One CTA per sequence,
// thread j owns column j with Wh[:,j] in registers, h broadcast via shared,
// two barriers per step, libm tanhf, 1-deep xi prefetch.
// ---------------------------------------------------------------------------
__global__ __launch_bounds__(128) void rnn_kernel(const float* __restrict__ Wh) {
    __shared__ __align__(16) float sh[HH];
    const int b = blockIdx.x;
    const int j = threadIdx.x;

    float w[HH];
#pragma unroll
    for (int k = 0; k < HH; k++) w[k] = Wh[k * HH + j];

    sh[j] = 0.f;
    const float* xip = g_xi + (size_t)b * SS * HH + j;
    float*       hp  = g_h  + (size_t)b * SS * HH + j;
    __syncthreads();

    float xi_cur = xip[0];
    for (int s = 0; s < SS; s++) {
        float xi_next = (s + 1 < SS) ? xip[(size_t)(s + 1) * HH] : 0.f;

        float a0 = xi_cur, a1 = 0.f, a2 = 0.f, a3 = 0.f;
        const float4* sh4 = (const float4*)sh;
#pragma unroll
        for (int k4 = 0; k4 < HH / 4; k4++) {
            float4 hv = sh4[k4];
            a0 = fmaf(hv.x, w[4 * k4 + 0], a0);
            a1 = fmaf(hv.y, w[4 * k4 + 1], a1);
            a2 = fmaf(hv.z, w[4 * k4 + 2], a2);
            a3 = fmaf(hv.w, w[4 * k4 + 3], a3);
        }
        float v  = (a0 + a1) + (a2 + a3);
        float hn = fmaxf(tanhf(v), 0.f);

        __syncthreads();
        sh[j] = hn;
        hp[(size_t)s * HH] = hn;
        xi_cur = xi_next;
        __syncthreads();
    }
}

extern "C" void kernel_launch(void* const* d_in, const int* in_sizes, int n_in,
                              void* d_out, int out_size) {
    const float* x  = (const float*)d_in[0];
    const float* Wi = (const float*)d_in[1];
    const float* Wh = (const float*)d_in[2];
    const float* b  = (const float*)d_in[3];
    const float* Wo = (const float*)d_in[4];
    const float* bo = (const float*)d_in[5];
    float* y = (float*)d_out;

    float *xi_ptr, *h_ptr;
    __nv_bfloat16 *wih, *wil, *woh, *wol;
    cudaGetSymbolAddress((void**)&xi_ptr, g_xi);
    cudaGetSymbolAddress((void**)&h_ptr,  g_h);
    cudaGetSymbolAddress((void**)&wih, g_wi_hi);
    cudaGetSymbolAddress((void**)&wil, g_wi_lo);
    cudaGetSymbolAddress((void**)&woh, g_wo_hi);
    cudaGetSymbolAddress((void**)&wol, g_wo_lo);

    cudaFuncSetAttribute(gemm_wt, cudaFuncAttributeMaxDynamicSharedMemorySize,
                         SM_TOT);

    prep_weights<<<(HH * HH + 255) / 256, 256>>>(Wi, Wo);
    gemm_wt<<<MM / MT, 128, SM_TOT>>>(x, wih, wil, b, xi_ptr);
    rnn_kernel<<<BB, 128>>>(Wh);
    gemm_wt<<<MM / MT, 128, SM_TOT>>>(h_ptr, woh, wol, bo, y);
}

// round 16
// speedup vs baseline: 1.0689x; 1.0172x over previous
#include <cuda_runtime.h>
#include <cuda_bf16.h>
#include <math.h>
#include <stdint.h>

#define BB 64
#define SS 2048
#define HH 128
#define MM (BB*SS)   // 131072
#define MT 64        // GEMM M-tile rows per CTA

// Scratch (no cudaMalloc allowed).
__device__ float g_xi[BB * SS * HH];
__device__ float g_h [BB * SS * HH];
// Weight tiles transposed to [n][k] row-major, split bf16 hi/lo.
__device__ __nv_bfloat16 g_wi_hi[HH * HH];
__device__ __nv_bfloat16 g_wi_lo[HH * HH];
__device__ __nv_bfloat16 g_wo_hi[HH * HH];
__device__ __nv_bfloat16 g_wo_lo[HH * HH];

__device__ __forceinline__ uint32_t smem_u32(const void* p) {
    uint32_t a;
    asm("{ .reg .u64 t; cvta.to.shared.u64 t, %1; cvt.u32.u64 %0, t; }"
        : "=r"(a) : "l"(p));
    return a;
}

__device__ __forceinline__ void mma_bf16(float* c, uint32_t a0, uint32_t a1,
                                         uint32_t a2, uint32_t a3,
                                         uint32_t b0, uint32_t b1) {
    asm volatile(
        "mma.sync.aligned.m16n8k16.row.col.f32.bf16.bf16.f32 "
        "{%0,%1,%2,%3}, {%4,%5,%6,%7}, {%8,%9}, {%0,%1,%2,%3};"
        : "+f"(c[0]), "+f"(c[1]), "+f"(c[2]), "+f"(c[3])
        : "r"(a0), "r"(a1), "r"(a2), "r"(a3), "r"(b0), "r"(b1));
}

__device__ __forceinline__ void ldsm4(uint32_t& r0, uint32_t& r1,
                                      uint32_t& r2, uint32_t& r3, uint32_t addr) {
    asm volatile("ldmatrix.sync.aligned.m8n8.x4.shared.b16 {%0,%1,%2,%3}, [%4];"
                 : "=r"(r0), "=r"(r1), "=r"(r2), "=r"(r3) : "r"(addr));
}

__device__ __forceinline__ uint32_t cvt_bf16x2(float xl, float yh) {
    uint32_t d;
    asm("cvt.rn.bf16x2.f32 %0, %1, %2;" : "=r"(d) : "f"(yh), "f"(xl));
    return d;
}

// ---------------------------------------------------------------------------
// Prep: W[k][n] (row-major KxN) -> Wt[n][k] row-major, split bf16 hi/lo.
// ---------------------------------------------------------------------------
__global__ void prep_weights(const float* __restrict__ Wi,
                             const float* __restrict__ Wo) {
    int idx = blockIdx.x * blockDim.x + threadIdx.x;
    if (idx >= HH * HH) return;
    int n = idx >> 7, k = idx & 127;
    {
        float v = Wi[k * HH + n];
        __nv_bfloat16 hi = __float2bfloat16(v);
        g_wi_hi[idx] = hi;
        g_wi_lo[idx] = __float2bfloat16(v - __bfloat162float(hi));
    }
    {
        float v = Wo[k * HH + n];
        __nv_bfloat16 hi = __float2bfloat16(v);
        g_wo_hi[idx] = hi;
        g_wo_lo[idx] = __float2bfloat16(v - __bfloat162float(hi));
    }
}

// ---------------------------------------------------------------------------
// Tensor-core split-bf16 GEMM (mma.sync + ldmatrix):
//   C[M,128] = A[M,128] @ W + bias; 3 terms Ah*Wh + Ah*Wl + Al*Wh, fp32 acc.
// R16: MT=64 rows, 256 threads, warp (wid&3 -> m16 strip, wid>>2 -> n64 half).
// Smem ~102.5 KB -> 2 CTAs x 256 threads per SM = 16 warps/SM (vs 8 before):
// two CTAs' phases interleave AND each phase has 2x warps of latency hiding.
// Load path and inner-loop math identical to the measured-53us R12 kernel.
// ---------------------------------------------------------------------------
#define PW 68
#define A_TILE_W (MT * PW * 4)     // 17408 B per A bf16x2 tile
#define W_TILE_W (HH * PW * 4)     // 34816 B per W bf16x2 tile
#define SM_BIAS 0
#define SM_AHI  512
#define SM_ALO  (SM_AHI + A_TILE_W)
#define SM_WHI  (SM_ALO + A_TILE_W)
#define SM_WLO  (SM_WHI + W_TILE_W)
#define SM_TOT  (SM_WLO + W_TILE_W)  // 104960 B ~= 102.5 KB

__global__ __launch_bounds__(256, 2) void gemm_wt(const float* __restrict__ A,
                                                  const __nv_bfloat16* __restrict__ Whi,
                                                  const __nv_bfloat16* __restrict__ Wlo,
                                                  const float* __restrict__ bias,
                                                  float* __restrict__ C) {
    extern __shared__ char smem[];
    uint32_t* sAhi  = (uint32_t*)(smem + SM_AHI);
    uint32_t* sAlo  = (uint32_t*)(smem + SM_ALO);
    uint32_t* sWhi  = (uint32_t*)(smem + SM_WHI);
    uint32_t* sWlo  = (uint32_t*)(smem + SM_WLO);
    float*    sbias = (float*)(smem + SM_BIAS);

    const int tid = threadIdx.x;          // 0..255
    const int wid = tid >> 5;             // 0..7
    const int l   = tid & 31;
    const int row0 = blockIdx.x * MT;

    // Weights: linear copy from pre-transposed global, re-pitch to PW.
    {
        const uint32_t* wh = (const uint32_t*)Whi;
        const uint32_t* wl = (const uint32_t*)Wlo;
#pragma unroll
        for (int i = 0; i < 32; i++) {
            int w   = tid + i * 256;            // 0..8191 u32 words
            int row = w >> 6, col = w & 63;
            sWhi[row * PW + col] = wh[w];
            sWlo[row * PW + col] = wl[w];
        }
    }
    if (tid < 32) ((float4*)sbias)[tid] = ((const float4*)bias)[tid];

    // A tile (64x128 fp32): coalesced float4 -> truncation hi/lo split.
    {
        const float4* Ag = (const float4*)(A + (size_t)row0 * HH);
#pragma unroll
        for (int i = 0; i < 8; i++) {
            int f4  = tid + i * 256;            // 0..2047
            int row = f4 >> 5;
            int c4  = f4 & 31;
            float4 v = Ag[f4];
            uint32_t bx = __float_as_uint(v.x), by = __float_as_uint(v.y);
            uint32_t bz = __float_as_uint(v.z), bw = __float_as_uint(v.w);
            uint32_t hi01 = __byte_perm(bx, by, 0x7632);
            uint32_t hi23 = __byte_perm(bz, bw, 0x7632);
            float lx = v.x - __uint_as_float(bx & 0xFFFF0000u);
            float ly = v.y - __uint_as_float(by & 0xFFFF0000u);
            float lz = v.z - __uint_as_float(bz & 0xFFFF0000u);
            float lw = v.w - __uint_as_float(bw & 0xFFFF0000u);
            uint32_t lo01 = cvt_bf16x2(lx, ly);
            uint32_t lo23 = cvt_bf16x2(lz, lw);
            int wo = row * PW + c4 * 2;
            *(uint2*)(sAhi + wo) = make_uint2(hi01, hi23);
            *(uint2*)(sAlo + wo) = make_uint2(lo01, lo23);
        }
    }
    __syncthreads();

    // Warp tile: (m16 strip, n64 half). 8 n8 tiles = 4 ldmatrix pairs,
    // 8 k16 steps, 3 terms. Same fragment math as R12.
    const int m0 = (wid & 3) * 16;
    const int nh = wid >> 2;              // 0/1: N half
    const int ra = (m0 + (l >> 2)) * PW + (l & 3);

    const int l8 = l & 7, lb = l >> 3;
    const int bword = (nh * 64 + (lb >> 1) * 8 + l8) * PW + (lb & 1) * 4;
    const uint32_t sb = smem_u32(smem);
    const uint32_t addrBhi = sb + SM_WHI + bword * 4;
    const uint32_t addrBlo = sb + SM_WLO + bword * 4;

    float acc[8][4];
#pragma unroll
    for (int nt = 0; nt < 8; nt++)
#pragma unroll
        for (int q = 0; q < 4; q++) acc[nt][q] = 0.f;

#pragma unroll
    for (int ks = 0; ks < 8; ks++) {
        const int kw = ks * 8;
        uint32_t ah0 = sAhi[ra + kw];
        uint32_t ah1 = sAhi[ra + 8 * PW + kw];
        uint32_t ah2 = sAhi[ra + kw + 4];
        uint32_t ah3 = sAhi[ra + 8 * PW + kw + 4];
        uint32_t al0 = sAlo[ra + kw];
        uint32_t al1 = sAlo[ra + 8 * PW + kw];
        uint32_t al2 = sAlo[ra + kw + 4];
        uint32_t al3 = sAlo[ra + 8 * PW + kw + 4];
#pragma unroll
        for (int p = 0; p < 4; p++) {
            const uint32_t ofs = (uint32_t)(p * 16 * PW + kw) * 4;
            uint32_t bh0, bh1, bh2, bh3, bl0, bl1, bl2, bl3;
            ldsm4(bh0, bh1, bh2, bh3, addrBhi + ofs);
            ldsm4(bl0, bl1, bl2, bl3, addrBlo + ofs);
            mma_bf16(acc[2 * p],     ah0, ah1, ah2, ah3, bh0, bh1);
            mma_bf16(acc[2 * p],     ah0, ah1, ah2, ah3, bl0, bl1);
            mma_bf16(acc[2 * p],     al0, al1, al2, al3, bh0, bh1);
            mma_bf16(acc[2 * p + 1], ah0, ah1, ah2, ah3, bh2, bh3);
            mma_bf16(acc[2 * p + 1], ah0, ah1, ah2, ah3, bl2, bl3);
            mma_bf16(acc[2 * p + 1], al0, al1, al2, al3, bh2, bh3);
        }
    }

    // Epilogue: c0,c1 -> (row, col..col+1); c2,c3 -> (row+8, ...).
    {
        const int rlo = row0 + m0 + (l >> 2);
        const int col0 = nh * 64 + (l & 3) * 2;
#pragma unroll
        for (int nt = 0; nt < 8; nt++) {
            int col = col0 + nt * 8;
            float2 b01 = {sbias[col], sbias[col + 1]};
            float2 o0 = {acc[nt][0] + b01.x, acc[nt][1] + b01.y};
            float2 o1 = {acc[nt][2] + b01.x, acc[nt][3] + b01.y};
            *(float2*)(C + (size_t)rlo * HH + col)       = o0;
            *(float2*)(C + (size_t)(rlo + 8) * HH + col) = o1;
        }
    }
}

// ---------------------------------------------------------------------------
// Recurrence: EXACT R3 kernel — FROZEN. (Measured 926us; all six attempted
// variations, including MUFU tanh alone, regressed.) One CTA per sequence,
// thread j owns column j with Wh[:,j] in registers, h broadcast via shared,
// two barriers per step, libm tanhf, 1-deep xi prefetch.
// ---------------------------------------------------------------------------
__global__ __launch_bounds__(128) void rnn_kernel(const float* __restrict__ Wh) {
    __shared__ __align__(16) float sh[HH];
    const int b = blockIdx.x;
    const int j = threadIdx.x;

    float w[HH];
#pragma unroll
    for (int k = 0; k < HH; k++) w[k] = Wh[k * HH + j];

    sh[j] = 0.f;
    const float* xip = g_xi + (size_t)b * SS * HH + j;
    float*       hp  = g_h  + (size_t)b * SS * HH + j;
    __syncthreads();

    float xi_cur = xip[0];
    for (int s = 0; s < SS; s++) {
        float xi_next = (s + 1 < SS) ? xip[(size_t)(s + 1) * HH] : 0.f;

        float a0 = xi_cur, a1 = 0.f, a2 = 0.f, a3 = 0.f;
        const float4* sh4 = (const float4*)sh;
#pragma unroll
        for (int k4 = 0; k4 < HH / 4; k4++) {
            float4 hv = sh4[k4];
            a0 = fmaf(hv.x, w[4 * k4 + 0], a0);
            a1 = fmaf(hv.y, w[4 * k4 + 1], a1);
            a2 = fmaf(hv.z, w[4 * k4 + 2], a2);
            a3 = fmaf(hv.w, w[4 * k4 + 3], a3);
        }
        float v  = (a0 + a1) + (a2 + a3);
        float hn = fmaxf(tanhf(v), 0.f);

        __syncthreads();
        sh[j] = hn;
        hp[(size_t)s * HH] = hn;
        xi_cur = xi_next;
        __syncthreads();
    }
}

extern "C" void kernel_launch(void* const* d_in, const int* in_sizes, int n_in,
                              void* d_out, int out_size) {
    const float* x  = (const float*)d_in[0];
    const float* Wi = (const float*)d_in[1];
    const float* Wh = (const float*)d_in[2];
    const float* b  = (const float*)d_in[3];
    const float* Wo = (const float*)d_in[4];
    const float* bo = (const float*)d_in[5];
    float* y = (float*)d_out;

    float *xi_ptr, *h_ptr;
    __nv_bfloat16 *wih, *wil, *woh, *wol;
    cudaGetSymbolAddress((void**)&xi_ptr, g_xi);
    cudaGetSymbolAddress((void**)&h_ptr,  g_h);
    cudaGetSymbolAddress((void**)&wih, g_wi_hi);
    cudaGetSymbolAddress((void**)&wil, g_wi_lo);
    cudaGetSymbolAddress((void**)&woh, g_wo_hi);
    cudaGetSymbolAddress((void**)&wol, g_wo_lo);

    cudaFuncSetAttribute(gemm_wt, cudaFuncAttributeMaxDynamicSharedMemorySize,
                         SM_TOT);

    prep_weights<<<(HH * HH + 255) / 256, 256>>>(Wi, Wo);
    gemm_wt<<<MM / MT, 256, SM_TOT>>>(x, wih, wil, b, xi_ptr);
    rnn_kernel<<<BB, 128>>>(Wh);
    gemm_wt<<<MM / MT, 256, SM_TOT>>>(h_ptr, woh, wol, bo, y);
}

// round 17
// speedup vs baseline: 1.0742x; 1.0050x over previous
#include <cuda_runtime.h>
#include <cuda_bf16.h>
#include <math.h>
#include <stdint.h>

#define BB 64
#define SS 2048
#define HH 128
#define MM (BB*SS)   // 131072

// Scratch (no cudaMalloc allowed).
__device__ float g_xi[BB * SS * HH];
__device__ float g_h [BB * SS * HH];
// Weight tiles transposed to [n][k] row-major, split bf16 hi/lo.
__device__ __nv_bfloat16 g_wi_hi[HH * HH];
__device__ __nv_bfloat16 g_wi_lo[HH * HH];
__device__ __nv_bfloat16 g_wo_hi[HH * HH];
__device__ __nv_bfloat16 g_wo_lo[HH * HH];

__device__ __forceinline__ uint32_t smem_u32(const void* p) {
    uint32_t a;
    asm("{ .reg .u64 t; cvta.to.shared.u64 t, %1; cvt.u32.u64 %0, t; }"
        : "=r"(a) : "l"(p));
    return a;
}

__device__ __forceinline__ void mma_bf16(float* c, uint32_t a0, uint32_t a1,
                                         uint32_t a2, uint32_t a3,
                                         uint32_t b0, uint32_t b1) {
    asm volatile(
        "mma.sync.aligned.m16n8k16.row.col.f32.bf16.bf16.f32 "
        "{%0,%1,%2,%3}, {%4,%5,%6,%7}, {%8,%9}, {%0,%1,%2,%3};"
        : "+f"(c[0]), "+f"(c[1]), "+f"(c[2]), "+f"(c[3])
        : "r"(a0), "r"(a1), "r"(a2), "r"(a3), "r"(b0), "r"(b1));
}

// ldmatrix x4: lane i supplies the address of row (i&7) of block (i>>3).
__device__ __forceinline__ void ldsm4(uint32_t& r0, uint32_t& r1,
                                      uint32_t& r2, uint32_t& r3, uint32_t addr) {
    asm volatile("ldmatrix.sync.aligned.m8n8.x4.shared.b16 {%0,%1,%2,%3}, [%4];"
                 : "=r"(r0), "=r"(r1), "=r"(r2), "=r"(r3) : "r"(addr));
}

// cvt.rn.bf16x2.f32: result = {hi16 = bf16(yh), lo16 = bf16(xl)}.
__device__ __forceinline__ uint32_t cvt_bf16x2(float xl, float yh) {
    uint32_t d;
    asm("cvt.rn.bf16x2.f32 %0, %1, %2;" : "=r"(d) : "f"(yh), "f"(xl));
    return d;
}

// ---------------------------------------------------------------------------
// Prep: W[k][n] (row-major KxN) -> Wt[n][k] row-major, split bf16 hi/lo.
// ---------------------------------------------------------------------------
__global__ void prep_weights(const float* __restrict__ Wi,
                             const float* __restrict__ Wo) {
    int idx = blockIdx.x * blockDim.x + threadIdx.x;
    if (idx >= HH * HH) return;
    int n = idx >> 7, k = idx & 127;
    {
        float v = Wi[k * HH + n];
        __nv_bfloat16 hi = __float2bfloat16(v);
        g_wi_hi[idx] = hi;
        g_wi_lo[idx] = __float2bfloat16(v - __bfloat162float(hi));
    }
    {
        float v = Wo[k * HH + n];
        __nv_bfloat16 hi = __float2bfloat16(v);
        g_wo_hi[idx] = hi;
        g_wo_lo[idx] = __float2bfloat16(v - __bfloat162float(hi));
    }
}

// ---------------------------------------------------------------------------
// Tensor-core split-bf16 GEMM (mma.sync + ldmatrix, base-target PTX):
//   C[M,128] = A[M,128] @ W + bias; 3 terms Ah*Wh + Ah*Wl + Al*Wh, fp32 acc.
// R17 = R12 config (MT=128, 256 thr, measured 53.3us) with ONE change:
// A-fragments loaded via ldmatrix.x4 (2 LDSM/k-step) instead of 8 scalar
// LDS.32 — cuts warp issue slots 576 -> 528 on an issue-floor-bound loop.
// ---------------------------------------------------------------------------
#define PW 68
#define TILE_W (HH * PW * 4)       // 34816 B per bf16x2 tile
#define SM_BIAS 0
#define SM_AHI  512
#define SM_ALO  (SM_AHI + TILE_W)
#define SM_WHI  (SM_ALO + TILE_W)
#define SM_WLO  (SM_WHI + TILE_W)
#define SM_TOT  (SM_WLO + TILE_W)  // ~137 KB

__global__ __launch_bounds__(256) void gemm_wt(const float* __restrict__ A,
                                               const __nv_bfloat16* __restrict__ Whi,
                                               const __nv_bfloat16* __restrict__ Wlo,
                                               const float* __restrict__ bias,
                                               float* __restrict__ C) {
    extern __shared__ char smem[];
    uint32_t* sAhi  = (uint32_t*)(smem + SM_AHI);
    uint32_t* sAlo  = (uint32_t*)(smem + SM_ALO);
    uint32_t* sWhi  = (uint32_t*)(smem + SM_WHI);
    uint32_t* sWlo  = (uint32_t*)(smem + SM_WLO);
    float*    sbias = (float*)(smem + SM_BIAS);

    const int tid = threadIdx.x;
    const int wid = tid >> 5;
    const int l   = tid & 31;
    const int row0 = blockIdx.x * 128;

    // Weights: linear copy from pre-transposed global, re-pitch to PW.
    {
        const uint32_t* wh = (const uint32_t*)Whi;
        const uint32_t* wl = (const uint32_t*)Wlo;
#pragma unroll
        for (int i = 0; i < 32; i++) {
            int w   = tid + i * 256;            // 0..8191 u32 words
            int row = w >> 6, col = w & 63;
            sWhi[row * PW + col] = wh[w];
            sWlo[row * PW + col] = wl[w];
        }
    }
    if (tid < 32) ((float4*)sbias)[tid] = ((const float4*)bias)[tid];

    // A tile: coalesced float4 loads -> truncation hi/lo split -> pitched stores.
    {
        const float4* Ag = (const float4*)(A + (size_t)row0 * HH);
#pragma unroll
        for (int i = 0; i < 16; i++) {
            int f4  = tid + i * 256;            // 0..4095
            int row = f4 >> 5;
            int c4  = f4 & 31;
            float4 v = Ag[f4];
            uint32_t bx = __float_as_uint(v.x), by = __float_as_uint(v.y);
            uint32_t bz = __float_as_uint(v.z), bw = __float_as_uint(v.w);
            uint32_t hi01 = __byte_perm(bx, by, 0x7632);
            uint32_t hi23 = __byte_perm(bz, bw, 0x7632);
            float lx = v.x - __uint_as_float(bx & 0xFFFF0000u);
            float ly = v.y - __uint_as_float(by & 0xFFFF0000u);
            float lz = v.z - __uint_as_float(bz & 0xFFFF0000u);
            float lw = v.w - __uint_as_float(bw & 0xFFFF0000u);
            uint32_t lo01 = cvt_bf16x2(lx, ly);
            uint32_t lo23 = cvt_bf16x2(lz, lw);
            int wo = row * PW + c4 * 2;
            *(uint2*)(sAhi + wo) = make_uint2(hi01, hi23);
            *(uint2*)(sAlo + wo) = make_uint2(lo01, lo23);
        }
    }
    __syncthreads();

    // Warp tile: m16 strip, 16 n8 tiles (8 ldmatrix pairs), 8 k16 steps, 3 terms.
    const int m0 = wid * 16;
    const uint32_t sb = smem_u32(smem);

    // A ldmatrix base: m16k16 blocks (m0-7,k0-7),(m8-15,k0-7),(m0-7,k8-15),
    // (m8-15,k8-15) -> lane l addresses row (l&7)+((l>>3)&1)*8, k-half (l>>4).
    const int aword = (m0 + (l & 7) + ((l >> 3) & 1) * 8) * PW + ((l >> 4) << 2);
    const uint32_t addrAhi = sb + SM_AHI + aword * 4;
    const uint32_t addrAlo = sb + SM_ALO + aword * 4;

    const int l8 = l & 7, lb = l >> 3;
    const int bword = ((lb >> 1) * 8 + l8) * PW + (lb & 1) * 4;
    const uint32_t addrBhi = sb + SM_WHI + bword * 4;
    const uint32_t addrBlo = sb + SM_WLO + bword * 4;

    float acc[16][4];
#pragma unroll
    for (int nt = 0; nt < 16; nt++)
#pragma unroll
        for (int q = 0; q < 4; q++) acc[nt][q] = 0.f;

#pragma unroll
    for (int ks = 0; ks < 8; ks++) {
        const uint32_t kofs = (uint32_t)(ks * 8) * 4;   // k16 = 8 words = 32B
        uint32_t ah0, ah1, ah2, ah3, al0, al1, al2, al3;
        ldsm4(ah0, ah1, ah2, ah3, addrAhi + kofs);
        ldsm4(al0, al1, al2, al3, addrAlo + kofs);
#pragma unroll
        for (int p = 0; p < 8; p++) {
            const uint32_t ofs = (uint32_t)(p * 16 * PW) * 4 + kofs;
            uint32_t bh0, bh1, bh2, bh3, bl0, bl1, bl2, bl3;
            ldsm4(bh0, bh1, bh2, bh3, addrBhi + ofs);
            ldsm4(bl0, bl1, bl2, bl3, addrBlo + ofs);
            mma_bf16(acc[2 * p],     ah0, ah1, ah2, ah3, bh0, bh1);
            mma_bf16(acc[2 * p],     ah0, ah1, ah2, ah3, bl0, bl1);
            mma_bf16(acc[2 * p],     al0, al1, al2, al3, bh0, bh1);
            mma_bf16(acc[2 * p + 1], ah0, ah1, ah2, ah3, bh2, bh3);
            mma_bf16(acc[2 * p + 1], ah0, ah1, ah2, ah3, bl2, bl3);
            mma_bf16(acc[2 * p + 1], al0, al1, al2, al3, bh2, bh3);
        }
    }

    // Epilogue: c0,c1 -> (row, col..col+1); c2,c3 -> (row+8, ...).
    {
        const int rlo = row0 + m0 + (l >> 2);
        const int col0 = (l & 3) * 2;
#pragma unroll
        for (int nt = 0; nt < 16; nt++) {
            int col = nt * 8 + col0;
            float2 b01 = {sbias[col], sbias[col + 1]};
            float2 o0 = {acc[nt][0] + b01.x, acc[nt][1] + b01.y};
            float2 o1 = {acc[nt][2] + b01.x, acc[nt][3] + b01.y};
            *(float2*)(C + (size_t)rlo * HH + col)       = o0;
            *(float2*)(C + (size_t)(rlo + 8) * HH + col) = o1;
        }
    }
}

// ---------------------------------------------------------------------------
// Recurrence: EXACT R3 kernel — FROZEN. (Measured 926us; all attempted
// variations regressed.) One CTA per sequence, thread j owns column j with
// Wh[:,j] in registers, h broadcast via shared, two barriers per step,
// libm tanhf, 1-deep xi prefetch.
// ---------------------------------------------------------------------------
__global__ __launch_bounds__(128) void rnn_kernel(const float* __restrict__ Wh) {
    __shared__ __align__(16) float sh[HH];
    const int b = blockIdx.x;
    const int j = threadIdx.x;

    float w[HH];
#pragma unroll
    for (int k = 0; k < HH; k++) w[k] = Wh[k * HH + j];

    sh[j] = 0.f;
    const float* xip = g_xi + (size_t)b * SS * HH + j;
    float*       hp  = g_h  + (size_t)b * SS * HH + j;
    __syncthreads();

    float xi_cur = xip[0];
    for (int s = 0; s < SS; s++) {
        float xi_next = (s + 1 < SS) ? xip[(size_t)(s + 1) * HH] : 0.f;

        float a0 = xi_cur, a1 = 0.f, a2 = 0.f, a3 = 0.f;
        const float4* sh4 = (const float4*)sh;
#pragma unroll
        for (int k4 = 0; k4 < HH / 4; k4++) {
            float4 hv = sh4[k4];
            a0 = fmaf(hv.x, w[4 * k4 + 0], a0);
            a1 = fmaf(hv.y, w[4 * k4 + 1], a1);
            a2 = fmaf(hv.z, w[4 * k4 + 2], a2);
            a3 = fmaf(hv.w, w[4 * k4 + 3], a3);
        }
        float v  = (a0 + a1) + (a2 + a3);
        float hn = fmaxf(tanhf(v), 0.f);

        __syncthreads();
        sh[j] = hn;
        hp[(size_t)s * HH] = hn;
        xi_cur = xi_next;
        __syncthreads();
    }
}

extern "C" void kernel_launch(void* const* d_in, const int* in_sizes, int n_in,
                              void* d_out, int out_size) {
    const float* x  = (const float*)d_in[0];
    const float* Wi = (const float*)d_in[1];
    const float* Wh = (const float*)d_in[2];
    const float* b  = (const float*)d_in[3];
    const float* Wo = (const float*)d_in[4];
    const float* bo = (const float*)d_in[5];
    float* y = (float*)d_out;

    float *xi_ptr, *h_ptr;
    __nv_bfloat16 *wih, *wil, *woh, *wol;
    cudaGetSymbolAddress((void**)&xi_ptr, g_xi);
    cudaGetSymbolAddress((void**)&h_ptr,  g_h);
    cudaGetSymbolAddress((void**)&wih, g_wi_hi);
    cudaGetSymbolAddress((void**)&wil, g_wi_lo);
    cudaGetSymbolAddress((void**)&woh, g_wo_hi);
    cudaGetSymbolAddress((void**)&wol, g_wo_lo);

    cudaFuncSetAttribute(gemm_wt, cudaFuncAttributeMaxDynamicSharedMemorySize,
                         SM_TOT);

    prep_weights<<<(HH * HH + 255) / 256, 256>>>(Wi, Wo);
    gemm_wt<<<MM / 128, 256, SM_TOT>>>(x, wih, wil, b, xi_ptr);
    rnn_kernel<<<BB, 128>>>(Wh);
    gemm_wt<<<MM / 128, 256, SM_TOT>>>(h_ptr, woh, wol, bo, y);
}